// round 1
// baseline (speedup 1.0000x reference)
#include <cuda_runtime.h>
#include <cstdio>

#define MAXN 500000
#define MAXE 1000000
#define NB_MAX 512
#define SCAN_T 1024
#define SCAN_TILE 2048

// ---------------- scratch (device globals; no allocations) ----------------
__device__ int g_deg[MAXN];
__device__ int g_rowptr[MAXN + 1];
__device__ int g_cursor[MAXN];
__device__ int g_adj[MAXE];
__device__ int g_bsums[NB_MAX];
__device__ float g_h1[MAXN * 32];
__device__ float g_h2[MAXN * 64];
__device__ float g_h3[MAXN * 64];

// ---------------- CSR build ----------------
__global__ void k_zero_deg(int n) {
    int t = blockIdx.x * blockDim.x + threadIdx.x;
    if (t < n) g_deg[t] = 0;
}

__global__ void k_count_deg(const int* __restrict__ ei, int nE) {
    int e = blockIdx.x * blockDim.x + threadIdx.x;
    if (e >= nE) return;
    int dst = ei[nE + e];
    atomicAdd(&g_deg[dst], 1);
}

__global__ void k_scan_reduce(int n) {
    __shared__ int sd[SCAN_T];
    int base = blockIdx.x * SCAN_TILE + threadIdx.x * 2;
    int s = 0;
    if (base < n) s += g_deg[base];
    if (base + 1 < n) s += g_deg[base + 1];
    sd[threadIdx.x] = s;
    __syncthreads();
    for (int d = SCAN_T / 2; d > 0; d >>= 1) {
        if (threadIdx.x < d) sd[threadIdx.x] += sd[threadIdx.x + d];
        __syncthreads();
    }
    if (threadIdx.x == 0) g_bsums[blockIdx.x] = sd[0];
}

__global__ void k_scan_mid(int nb, int nN) {
    int run = 0;
    for (int i = 0; i < nb; i++) {
        int t = g_bsums[i];
        g_bsums[i] = run;
        run += t;
    }
    g_rowptr[nN] = run;
}

__global__ void k_scan_final(int n) {
    __shared__ int sd[SCAN_T];
    int tid = threadIdx.x;
    int base = blockIdx.x * SCAN_TILE + tid * 2;
    int t0 = (base < n) ? g_deg[base] : 0;
    int t1 = (base + 1 < n) ? g_deg[base + 1] : 0;
    int ts = t0 + t1;
    sd[tid] = ts;
    __syncthreads();
    // Hillis-Steele inclusive scan
    for (int d = 1; d < SCAN_T; d <<= 1) {
        int v = (tid >= d) ? sd[tid - d] : 0;
        __syncthreads();
        sd[tid] += v;
        __syncthreads();
    }
    int excl = sd[tid] - ts + g_bsums[blockIdx.x];
    if (base < n)     { g_rowptr[base]     = excl;      g_cursor[base]     = excl; }
    if (base + 1 < n) { g_rowptr[base + 1] = excl + t0; g_cursor[base + 1] = excl + t0; }
}

__global__ void k_fill_adj(const int* __restrict__ ei, const int* __restrict__ et, int nE) {
    int e = blockIdx.x * blockDim.x + threadIdx.x;
    if (e >= nE) return;
    int src = ei[e];
    int dst = ei[nE + e];
    int r = et[e];
    int pos = atomicAdd(&g_cursor[dst], 1);
    g_adj[pos] = (src << 2) | r;
}

// ---------------- pre-MLP: h1 = relu(concat(shape,color) @ pre_w + pre_b) ----------------
__global__ void k_pre(const int* __restrict__ x,
                      const float* __restrict__ shape_emb,
                      const float* __restrict__ color_emb,
                      const float* __restrict__ pre_w,
                      const float* __restrict__ pre_b,
                      int n) {
    int t = blockIdx.x * blockDim.x + threadIdx.x;
    if (t >= n * 32) return;
    int node = t >> 5;
    int f = t & 31;
    int si = __ldg(&x[2 * node]);
    int ci = __ldg(&x[2 * node + 1]);
    float s = __ldg(&pre_b[f]);
#pragma unroll
    for (int k = 0; k < 8; k++)
        s += __ldg(&shape_emb[si * 8 + k]) * __ldg(&pre_w[k * 32 + f]);
#pragma unroll
    for (int k = 0; k < 8; k++)
        s += __ldg(&color_emb[ci * 8 + k]) * __ldg(&pre_w[(8 + k) * 32 + f]);
    g_h1[node * 32 + f] = fmaxf(s, 0.f);
}

// ---------------- RGCN layer: warp per node, gather + fused GEMM ----------------
// out_i = relu( b + h_i @ root + sum_r mean_{j in N_r(i)} h_j @ W_r )
template <int F_IN>
__global__ void __launch_bounds__(256)
k_layer(const float* __restrict__ h_in, float* __restrict__ h_out,
        const float* __restrict__ w_rel,    // [3, F_IN, 64]
        const float* __restrict__ w_root,   // [F_IN, 64]
        const float* __restrict__ bias,     // [64]
        int n) {
    extern __shared__ float Wsm[];  // [4*F_IN][64]: w_rel(3 blocks) then root
    const int NW = 4 * F_IN * 64;
    for (int i = threadIdx.x; i < NW; i += blockDim.x)
        Wsm[i] = (i < 3 * F_IN * 64) ? w_rel[i] : w_root[i - 3 * F_IN * 64];
    __syncthreads();

    const int lane = threadIdx.x & 31;
    const int warp = threadIdx.x >> 5;
    const int R = F_IN / 32;  // accumulator regs per relation

    const float b0 = __ldg(&bias[2 * lane]);
    const float b1 = __ldg(&bias[2 * lane + 1]);

    for (int node = blockIdx.x * 8 + warp; node < n; node += gridDim.x * 8) {
        float a0[R], a1[R], a2[R], hh[R];
#pragma unroll
        for (int j = 0; j < R; j++) {
            a0[j] = 0.f; a1[j] = 0.f; a2[j] = 0.f;
            hh[j] = __ldg(&h_in[node * F_IN + 32 * j + lane]);
        }
        int c0 = 0, c1 = 0, c2 = 0;
        int rs = __ldg(&g_rowptr[node]);
        int re = __ldg(&g_rowptr[node + 1]);
        for (int e = rs; e < re; ++e) {
            int p = __ldg(&g_adj[e]);
            int src = p >> 2;
            int r = p & 3;
            float v[R];
#pragma unroll
            for (int j = 0; j < R; j++) v[j] = __ldg(&h_in[src * F_IN + 32 * j + lane]);
            if (r == 0) {
                c0++;
#pragma unroll
                for (int j = 0; j < R; j++) a0[j] += v[j];
            } else if (r == 1) {
                c1++;
#pragma unroll
                for (int j = 0; j < R; j++) a1[j] += v[j];
            } else {
                c2++;
#pragma unroll
                for (int j = 0; j < R; j++) a2[j] += v[j];
            }
        }
        float s0 = 1.f / (float)((c0 > 1) ? c0 : 1);
        float s1 = 1.f / (float)((c1 > 1) ? c1 : 1);
        float s2 = 1.f / (float)((c2 > 1) ? c2 : 1);
#pragma unroll
        for (int j = 0; j < R; j++) { a0[j] *= s0; a1[j] *= s1; a2[j] *= s2; }

        float out0 = b0, out1 = b1;
#pragma unroll
        for (int k = 0; k < F_IN; k++) {
            const int j = k >> 5, sl = k & 31;
            float v0 = __shfl_sync(0xffffffffu, a0[j], sl);
            float v1 = __shfl_sync(0xffffffffu, a1[j], sl);
            float v2 = __shfl_sync(0xffffffffu, a2[j], sl);
            float vh = __shfl_sync(0xffffffffu, hh[j], sl);
            float2 w0 = *(const float2*)&Wsm[(0 * F_IN + k) * 64 + 2 * lane];
            float2 w1 = *(const float2*)&Wsm[(1 * F_IN + k) * 64 + 2 * lane];
            float2 w2 = *(const float2*)&Wsm[(2 * F_IN + k) * 64 + 2 * lane];
            float2 wr = *(const float2*)&Wsm[(3 * F_IN + k) * 64 + 2 * lane];
            out0 += v0 * w0.x + v1 * w1.x + v2 * w2.x + vh * wr.x;
            out1 += v0 * w0.y + v1 * w1.y + v2 * w2.y + vh * wr.y;
        }
        float2 res = make_float2(fmaxf(out0, 0.f), fmaxf(out1, 0.f));
        *(float2*)&h_out[node * 64 + 2 * lane] = res;
    }
}

// ---------------- classifier: out[g] = h3[ptr[g+1]-1] @ cls_w + cls_b ----------------
__global__ void k_cls(const int* __restrict__ ptr,
                      const float* __restrict__ cls_w,
                      const float* __restrict__ cls_b,
                      float* __restrict__ out,
                      int nG) {
    int t = blockIdx.x * blockDim.x + threadIdx.x;
    if (t >= nG * 10) return;
    int g = t / 10;
    int c = t % 10;
    int idx = __ldg(&ptr[g + 1]) - 1;
    const float* hrow = &g_h3[idx * 64];
    float s = __ldg(&cls_b[c]);
#pragma unroll
    for (int k = 0; k < 64; k++) s += hrow[k] * __ldg(&cls_w[k * 10 + c]);
    out[t] = s;
}

// ---------------- launch ----------------
extern "C" void kernel_launch(void* const* d_in, const int* in_sizes, int n_in,
                              void* d_out, int out_size) {
    const int* x          = (const int*)d_in[0];
    const int* edge_index = (const int*)d_in[1];
    const int* edge_type  = (const int*)d_in[2];
    const int* ptr        = (const int*)d_in[3];
    const float* shape_emb = (const float*)d_in[4];
    const float* color_emb = (const float*)d_in[5];
    const float* pre_w    = (const float*)d_in[6];
    const float* pre_b    = (const float*)d_in[7];
    const float* w1_rel   = (const float*)d_in[8];
    const float* w1_root  = (const float*)d_in[9];
    const float* b1       = (const float*)d_in[10];
    const float* w2_rel   = (const float*)d_in[11];
    const float* w2_root  = (const float*)d_in[12];
    const float* b2       = (const float*)d_in[13];
    const float* cls_w    = (const float*)d_in[14];
    const float* cls_b    = (const float*)d_in[15];
    float* out = (float*)d_out;

    const int nN = in_sizes[0] / 2;       // x is [N,2]
    const int nE = in_sizes[2];           // edge_type is [E]
    const int nG = in_sizes[3] - 1;       // ptr is [G+1]
    const int nb = (nN + SCAN_TILE - 1) / SCAN_TILE;

    float *h1, *h2, *h3;
    cudaGetSymbolAddress((void**)&h1, g_h1);
    cudaGetSymbolAddress((void**)&h2, g_h2);
    cudaGetSymbolAddress((void**)&h3, g_h3);

    const int smem1 = 4 * 32 * 64 * (int)sizeof(float);   // 32 KB
    const int smem2 = 4 * 64 * 64 * (int)sizeof(float);   // 64 KB
    cudaFuncSetAttribute(k_layer<32>, cudaFuncAttributeMaxDynamicSharedMemorySize, smem1);
    cudaFuncSetAttribute(k_layer<64>, cudaFuncAttributeMaxDynamicSharedMemorySize, smem2);

    // CSR by destination
    k_zero_deg<<<(nN + 255) / 256, 256>>>(nN);
    k_count_deg<<<(nE + 255) / 256, 256>>>(edge_index, nE);
    k_scan_reduce<<<nb, SCAN_T>>>(nN);
    k_scan_mid<<<1, 1>>>(nb, nN);
    k_scan_final<<<nb, SCAN_T>>>(nN);
    k_fill_adj<<<(nE + 255) / 256, 256>>>(edge_index, edge_type, nE);

    // Feature pipeline
    k_pre<<<(nN * 32 + 255) / 256, 256>>>(x, shape_emb, color_emb, pre_w, pre_b, nN);
    k_layer<32><<<148 * 7, 256, smem1>>>(h1, h2, w1_rel, w1_root, b1, nN);
    k_layer<64><<<148 * 3, 256, smem2>>>(h2, h3, w2_rel, w2_root, b2, nN);
    k_cls<<<(nG * 10 + 255) / 256, 256>>>(ptr, cls_w, cls_b, out, nG);
}

// round 4
// speedup vs baseline: 1.9750x; 1.9750x over previous
#include <cuda_runtime.h>
#include <cstdio>

#define MAXN 500000
#define MAXE 1000000
#define NB_MAX 512
#define SCAN_T 1024
#define SCAN_TILE 2048
#define NSM 152

// ---------------- scratch (device globals; no allocations) ----------------
__device__ int g_deg[MAXN];
__device__ int g_rowptr[MAXN + 1];
__device__ int g_cursor[MAXN];
__device__ int g_adj[MAXE];
__device__ int g_bsums[NB_MAX];
__device__ float g_h1[MAXN * 32];
__device__ float g_h2[MAXN * 64];
__device__ float g_h3[MAXN * 64];
__device__ float g_cat[(size_t)MAXN * 256];   // concat [agg0,agg1,agg2,h] rows

// ---------------- helpers ----------------
__device__ __forceinline__ float2 ffma2(float a, float2 b, float2 c) {
    unsigned long long av, bv, cv, dv;
    unsigned int au = __float_as_uint(a);
    asm("mov.b64 %0, {%1, %1};" : "=l"(av) : "r"(au));
    bv = *reinterpret_cast<unsigned long long*>(&b);
    cv = *reinterpret_cast<unsigned long long*>(&c);
    asm("fma.rn.f32x2 %0, %1, %2, %3;" : "=l"(dv) : "l"(av), "l"(bv), "l"(cv));
    return *reinterpret_cast<float2*>(&dv);
}

__device__ __forceinline__ unsigned int smem_u32(const void* p) {
    return (unsigned int)__cvta_generic_to_shared(p);
}

#define CP_ASYNC16(dst, src) \
    asm volatile("cp.async.cg.shared.global [%0], [%1], 16;" :: "r"(dst), "l"(src))
#define CP_COMMIT() asm volatile("cp.async.commit_group;")
#define CP_WAIT0()  asm volatile("cp.async.wait_group 0;")

// ---------------- CSR build ----------------
__global__ void k_zero_deg(int n) {
    int t = blockIdx.x * blockDim.x + threadIdx.x;
    if (t < n) g_deg[t] = 0;
}

__global__ void k_count_deg(const int* __restrict__ ei, int nE) {
    int e = blockIdx.x * blockDim.x + threadIdx.x;
    if (e >= nE) return;
    atomicAdd(&g_deg[ei[nE + e]], 1);
}

__global__ void k_scan_reduce(int n) {
    __shared__ int sd[SCAN_T];
    int base = blockIdx.x * SCAN_TILE + threadIdx.x * 2;
    int s = 0;
    if (base < n) s += g_deg[base];
    if (base + 1 < n) s += g_deg[base + 1];
    sd[threadIdx.x] = s;
    __syncthreads();
    for (int d = SCAN_T / 2; d > 0; d >>= 1) {
        if (threadIdx.x < d) sd[threadIdx.x] += sd[threadIdx.x + d];
        __syncthreads();
    }
    if (threadIdx.x == 0) g_bsums[blockIdx.x] = sd[0];
}

__global__ void k_scan_mid(int nb, int nN) {
    int run = 0;
    for (int i = 0; i < nb; i++) {
        int t = g_bsums[i];
        g_bsums[i] = run;
        run += t;
    }
    g_rowptr[nN] = run;
}

__global__ void k_scan_final(int n) {
    __shared__ int sd[SCAN_T];
    int tid = threadIdx.x;
    int base = blockIdx.x * SCAN_TILE + tid * 2;
    int t0 = (base < n) ? g_deg[base] : 0;
    int t1 = (base + 1 < n) ? g_deg[base + 1] : 0;
    int ts = t0 + t1;
    sd[tid] = ts;
    __syncthreads();
    for (int d = 1; d < SCAN_T; d <<= 1) {
        int v = (tid >= d) ? sd[tid - d] : 0;
        __syncthreads();
        sd[tid] += v;
        __syncthreads();
    }
    int excl = sd[tid] - ts + g_bsums[blockIdx.x];
    if (base < n)     { g_rowptr[base]     = excl;      g_cursor[base]     = excl; }
    if (base + 1 < n) { g_rowptr[base + 1] = excl + t0; g_cursor[base + 1] = excl + t0; }
}

__global__ void k_fill_adj(const int* __restrict__ ei, const int* __restrict__ et, int nE) {
    int e = blockIdx.x * blockDim.x + threadIdx.x;
    if (e >= nE) return;
    int src = ei[e];
    int dst = ei[nE + e];
    int r = et[e];
    int pos = atomicAdd(&g_cursor[dst], 1);
    g_adj[pos] = (src << 2) | r;
}

// ---------------- pre-MLP ----------------
__global__ void k_pre(const int* __restrict__ x,
                      const float* __restrict__ shape_emb,
                      const float* __restrict__ color_emb,
                      const float* __restrict__ pre_w,
                      const float* __restrict__ pre_b,
                      int n) {
    int t = blockIdx.x * blockDim.x + threadIdx.x;
    if (t >= n * 32) return;
    int node = t >> 5;
    int f = t & 31;
    int si = __ldg(&x[2 * node]);
    int ci = __ldg(&x[2 * node + 1]);
    float s = __ldg(&pre_b[f]);
#pragma unroll
    for (int k = 0; k < 8; k++)
        s += __ldg(&shape_emb[si * 8 + k]) * __ldg(&pre_w[k * 32 + f]);
#pragma unroll
    for (int k = 0; k < 8; k++)
        s += __ldg(&color_emb[ci * 8 + k]) * __ldg(&pre_w[(8 + k) * 32 + f]);
    g_h1[node * 32 + f] = fmaxf(s, 0.f);
}

// ---------------- aggregation: warp per node, writes concat row [4F] ----------------
template <int F>
__global__ void __launch_bounds__(256)
k_agg(const float* __restrict__ h_in, int n) {
    constexpr int R = F / 32;
    int node = blockIdx.x * 8 + (threadIdx.x >> 5);
    if (node >= n) return;
    const int lane = threadIdx.x & 31;

    float hh[R], a0[R], a1[R], a2[R];
#pragma unroll
    for (int j = 0; j < R; j++) {
        a0[j] = 0.f; a1[j] = 0.f; a2[j] = 0.f;
        hh[j] = __ldg(&h_in[(size_t)node * F + 32 * j + lane]);
    }
    int c0 = 0, c1 = 0, c2 = 0;
    int rs = __ldg(&g_rowptr[node]);
    int re = __ldg(&g_rowptr[node + 1]);
    for (int e = rs; e < re; ++e) {
        int p = __ldg(&g_adj[e]);
        int src = p >> 2;
        int r = p & 3;
        float v[R];
#pragma unroll
        for (int j = 0; j < R; j++) v[j] = __ldg(&h_in[(size_t)src * F + 32 * j + lane]);
        if (r == 0) { c0++;
#pragma unroll
            for (int j = 0; j < R; j++) a0[j] += v[j];
        } else if (r == 1) { c1++;
#pragma unroll
            for (int j = 0; j < R; j++) a1[j] += v[j];
        } else { c2++;
#pragma unroll
            for (int j = 0; j < R; j++) a2[j] += v[j];
        }
    }
    float s0 = 1.f / (float)((c0 > 1) ? c0 : 1);
    float s1 = 1.f / (float)((c1 > 1) ? c1 : 1);
    float s2 = 1.f / (float)((c2 > 1) ? c2 : 1);

    float* row = g_cat + (size_t)node * (4 * F);
#pragma unroll
    for (int j = 0; j < R; j++) {
        row[0 * F + 32 * j + lane] = a0[j] * s0;
        row[1 * F + 32 * j + lane] = a1[j] * s1;
        row[2 * F + 32 * j + lane] = a2[j] * s2;
        row[3 * F + 32 * j + lane] = hh[j];
    }
}

// ---------------- GEMM: C[N,64] = relu(Acat[N,K] @ [w_rel;w_root] + b) ----------------
// Persistent blocks; W in smem once per block; A chunks cp.async double-buffered;
// per warp: 8 nodes x 64 outputs, f32x2 packed FMA.
template <int K>
__global__ void __launch_bounds__(256)
k_gemm(const float* __restrict__ A,
       const float* __restrict__ w_rel, const float* __restrict__ w_root,
       const float* __restrict__ bias,
       float* __restrict__ C, int n) {
    constexpr int F = K / 4;
    constexpr int KC = 64;          // K-chunk
    constexpr int NC = K / KC;      // chunks
    constexpr int AP = 68;          // padded A row (floats) — conflict-free STS

    extern __shared__ float sm[];
    float* W_sm = sm;                       // [K][64]
    float* A_sm = sm + K * 64;              // [2][64][AP]

    for (int i = threadIdx.x; i < K * 64; i += 256)
        W_sm[i] = (i < 3 * F * 64) ? w_rel[i] : w_root[i - 3 * F * 64];

    const int lane = threadIdx.x & 31;
    const int warp = threadIdx.x >> 5;
    const float2 bb = *(const float2*)&bias[2 * lane];

    const int nloc = threadIdx.x >> 2;      // 0..63 node slot for loads
    const int seg  = threadIdx.x & 3;       // 16-float segment
    const unsigned int a_base = smem_u32(A_sm);

    for (int base = blockIdx.x * 64; base < n; base += gridDim.x * 64) {
        // prefetch chunk 0
        {
            int node = min(base + nloc, n - 1);
            const float* src = A + (size_t)node * K + seg * 16;
            unsigned int dst = a_base + (unsigned int)((nloc * AP + seg * 16) * 4);
#pragma unroll
            for (int v = 0; v < 4; v++) CP_ASYNC16(dst + v * 16, src + v * 4);
        }
        CP_COMMIT();

        float2 acc[8];
#pragma unroll
        for (int i = 0; i < 8; i++) acc[i] = make_float2(0.f, 0.f);

        for (int c = 0; c < NC; c++) {
            CP_WAIT0();
            __syncthreads();
            if (c + 1 < NC) {
                int node = min(base + nloc, n - 1);
                const float* src = A + (size_t)node * K + (c + 1) * KC + seg * 16;
                unsigned int dst = a_base +
                    (unsigned int)((((c + 1) & 1) * 64 * AP + nloc * AP + seg * 16) * 4);
#pragma unroll
                for (int v = 0; v < 4; v++) CP_ASYNC16(dst + v * 16, src + v * 4);
                CP_COMMIT();
            }
            const float* Ab = A_sm + (c & 1) * 64 * AP + (warp * 8) * AP;
            const float* Wb = W_sm + c * KC * 64;
#pragma unroll
            for (int k4 = 0; k4 < KC / 4; k4++) {
                float2 w0 = *(const float2*)&Wb[(4 * k4 + 0) * 64 + 2 * lane];
                float2 w1 = *(const float2*)&Wb[(4 * k4 + 1) * 64 + 2 * lane];
                float2 w2 = *(const float2*)&Wb[(4 * k4 + 2) * 64 + 2 * lane];
                float2 w3 = *(const float2*)&Wb[(4 * k4 + 3) * 64 + 2 * lane];
#pragma unroll
                for (int i = 0; i < 8; i++) {
                    float4 a = *(const float4*)&Ab[i * AP + 4 * k4];
                    acc[i] = ffma2(a.x, w0, acc[i]);
                    acc[i] = ffma2(a.y, w1, acc[i]);
                    acc[i] = ffma2(a.z, w2, acc[i]);
                    acc[i] = ffma2(a.w, w3, acc[i]);
                }
            }
            __syncthreads();
        }
#pragma unroll
        for (int i = 0; i < 8; i++) {
            int node = base + warp * 8 + i;
            if (node < n) {
                float2 r;
                r.x = fmaxf(acc[i].x + bb.x, 0.f);
                r.y = fmaxf(acc[i].y + bb.y, 0.f);
                *(float2*)&C[(size_t)node * 64 + 2 * lane] = r;
            }
        }
    }
}

// ---------------- classifier ----------------
__global__ void k_cls(const int* __restrict__ ptr,
                      const float* __restrict__ cls_w,
                      const float* __restrict__ cls_b,
                      float* __restrict__ out,
                      int nG) {
    int t = blockIdx.x * blockDim.x + threadIdx.x;
    if (t >= nG * 10) return;
    int g = t / 10;
    int c = t % 10;
    int idx = __ldg(&ptr[g + 1]) - 1;
    const float* hrow = &g_h3[(size_t)idx * 64];
    float s = __ldg(&cls_b[c]);
#pragma unroll
    for (int k = 0; k < 64; k++) s += hrow[k] * __ldg(&cls_w[k * 10 + c]);
    out[t] = s;
}

// ---------------- launch ----------------
extern "C" void kernel_launch(void* const* d_in, const int* in_sizes, int n_in,
                              void* d_out, int out_size) {
    const int* x          = (const int*)d_in[0];
    const int* edge_index = (const int*)d_in[1];
    const int* edge_type  = (const int*)d_in[2];
    const int* ptr        = (const int*)d_in[3];
    const float* shape_emb = (const float*)d_in[4];
    const float* color_emb = (const float*)d_in[5];
    const float* pre_w    = (const float*)d_in[6];
    const float* pre_b    = (const float*)d_in[7];
    const float* w1_rel   = (const float*)d_in[8];
    const float* w1_root  = (const float*)d_in[9];
    const float* b1       = (const float*)d_in[10];
    const float* w2_rel   = (const float*)d_in[11];
    const float* w2_root  = (const float*)d_in[12];
    const float* b2       = (const float*)d_in[13];
    const float* cls_w    = (const float*)d_in[14];
    const float* cls_b    = (const float*)d_in[15];
    float* out = (float*)d_out;

    const int nN = in_sizes[0] / 2;
    const int nE = in_sizes[2];
    const int nG = in_sizes[3] - 1;
    const int nb = (nN + SCAN_TILE - 1) / SCAN_TILE;

    float *h1, *h2, *h3, *cat;
    cudaGetSymbolAddress((void**)&h1, g_h1);
    cudaGetSymbolAddress((void**)&h2, g_h2);
    cudaGetSymbolAddress((void**)&h3, g_h3);
    cudaGetSymbolAddress((void**)&cat, g_cat);

    const int smem_g1 = 128 * 64 * 4 + 2 * 64 * 68 * 4;   // 67584
    const int smem_g2 = 256 * 64 * 4 + 2 * 64 * 68 * 4;   // 100352
    cudaFuncSetAttribute(k_gemm<128>, cudaFuncAttributeMaxDynamicSharedMemorySize, smem_g1);
    cudaFuncSetAttribute(k_gemm<256>, cudaFuncAttributeMaxDynamicSharedMemorySize, smem_g2);

    // CSR by destination
    k_zero_deg<<<(nN + 255) / 256, 256>>>(nN);
    k_count_deg<<<(nE + 255) / 256, 256>>>(edge_index, nE);
    k_scan_reduce<<<nb, SCAN_T>>>(nN);
    k_scan_mid<<<1, 1>>>(nb, nN);
    k_scan_final<<<nb, SCAN_T>>>(nN);
    k_fill_adj<<<(nE + 255) / 256, 256>>>(edge_index, edge_type, nE);

    // Feature pipeline
    k_pre<<<(nN * 32 + 255) / 256, 256>>>(x, shape_emb, color_emb, pre_w, pre_b, nN);

    k_agg<32><<<(nN + 7) / 8, 256>>>(h1, nN);
    k_gemm<128><<<NSM * 3, 256, smem_g1>>>(cat, w1_rel, w1_root, b1, h2, nN);

    k_agg<64><<<(nN + 7) / 8, 256>>>(h2, nN);
    k_gemm<256><<<NSM * 2, 256, smem_g2>>>(cat, w2_rel, w2_root, b2, h3, nN);

    k_cls<<<(nG * 10 + 255) / 256, 256>>>(ptr, cls_w, cls_b, out, nG);
}